// round 8
// baseline (speedup 1.0000x reference)
#include <cuda_runtime.h>
#include <cstdint>

// ---------------- scratch (device globals; no allocation allowed) ------------
__device__ float g_k  [16LL * 1024 * 512];   //  33.5 MB
__device__ float g_v  [16LL * 1024 * 512];   //  33.5 MB
__device__ float g_q  [16LL * 2048 * 512];   //  67 MB
__device__ float g_att[16LL * 2048 * 1024];  // 134 MB
__device__ float g_val[16LL * 2048 * 512];   //  67 MB
__device__ int   g_len[16];

// -------- lengths dtype sniffing (reference says int64; JAX x64-off -> int32)
__global__ void normalize_lengths(const void* __restrict__ lp)
{
    const long long* l8 = (const long long*)lp;
    const int*       l4 = (const int*)lp;
    bool ok64 = true;
    for (int i = 0; i < 8; ++i) {
        long long v = l8[i];
        if (v < 1 || v > 1024) ok64 = false;
    }
    if (ok64) {
        for (int i = 0; i < 16; ++i) g_len[i] = (int)l8[i];
    } else {
        for (int i = 0; i < 16; ++i) g_len[i] = l4[i];
    }
}

// ---------------------------------------------------------------------------
// tf32 helpers
__device__ __forceinline__ unsigned f2tf(float x) {
    unsigned u;
    asm("cvt.rna.tf32.f32 %0, %1;" : "=r"(u) : "f"(x));
    return u;
}

__device__ __forceinline__ void mma8(float* c, const unsigned* a,
                                     unsigned b0, unsigned b1) {
    asm volatile(
        "mma.sync.aligned.m16n8k8.row.col.f32.tf32.tf32.f32 "
        "{%0,%1,%2,%3},{%4,%5,%6,%7},{%8,%9},{%0,%1,%2,%3};"
        : "+f"(c[0]), "+f"(c[1]), "+f"(c[2]), "+f"(c[3])
        : "r"(a[0]), "r"(a[1]), "r"(a[2]), "r"(a[3]), "r"(b0), "r"(b1));
}

// ---------------------------------------------------------------------------
// Unified tf32 tensor-core GEMM, 128x128x16 CTA tiles, 128 threads
// (4 warps 2m x 2n), warp tile 64x64, m16n8k8. Double-buffered smem,
// LDG register prefetch, 2 CTAs/SM.
//
// AT=0: A row-major [M,K]  (m rows, k contig)  -> smem As[m][20]
// AT=1: A k-major  [K,M]   (k rows, m contig)  -> smem As[k][136]
// BT=0: B [K,N]            (k rows, n contig)  -> smem Bs[k][136]
// BT=1: B^T [N,K]          (n rows, k contig)  -> smem Bs[n][20]
// EPI=0: C = alpha*(A@B) + bias[col] (bias optional), row-major ldc
// EPI=2: mel permute: rows are mel indices, cols are t
template<int AT, int BT, int EPI>
__global__ __launch_bounds__(128, 2) void tc_gemm(
    const float* __restrict__ A, const float* __restrict__ Bm,
    const float* __restrict__ bias, float* __restrict__ C,
    int K, int lda, int ldb, int ldc,
    long long sA, long long sB, long long sC, float alpha)
{
    constexpr int ASZ = AT ? 16 * 136 : 128 * 20;
    constexpr int BSZ = BT ? 128 * 20 : 16 * 136;
    __shared__ unsigned smA[2][ASZ];
    __shared__ unsigned smB[2][BSZ];

    A  += blockIdx.z * sA;
    Bm += blockIdx.z * sB;
    const int tid  = threadIdx.x;
    const int lane = tid & 31, warp = tid >> 5;
    const int g  = lane >> 2, tg = lane & 3;
    const int wm = warp & 1,  wn = warp >> 1;          // 2 x 2 warps
    const int r0 = blockIdx.y * 128, c0 = blockIdx.x * 128;

    const float* aptr[4]; unsigned adst[4];
    const float* bptr[4]; unsigned bdst[4];
    #pragma unroll
    for (int r = 0; r < 4; ++r) {
        int i = tid + 128 * r;                          // 0..511, 4 elems each
        if (!AT) { int m = i >> 2, kq = (i & 3) * 4;
                   aptr[r] = A + (long long)(r0 + m) * lda + kq;
                   adst[r] = m * 20 + kq; }
        else     { int k = i >> 5, m4 = (i & 31) * 4;
                   aptr[r] = A + (long long)k * lda + r0 + m4;
                   adst[r] = k * 136 + m4; }
        if (!BT) { int k = i >> 5, n4 = (i & 31) * 4;
                   bptr[r] = Bm + (long long)k * ldb + c0 + n4;
                   bdst[r] = k * 136 + n4; }
        else     { int n = i >> 2, kq = (i & 3) * 4;
                   bptr[r] = Bm + (long long)(c0 + n) * ldb + kq;
                   bdst[r] = n * 20 + kq; }
    }
    const long long adv_a = AT ? 16LL * lda : 16LL;
    const long long adv_b = BT ? 16LL : 16LL * ldb;

    float acc[4][8][4] = {};
    const int nIter = K >> 4;

    float4 pa[4], pb[4];
    #pragma unroll
    for (int r = 0; r < 4; ++r) {
        pa[r] = *(const float4*)aptr[r];
        pb[r] = *(const float4*)bptr[r];
    }

    int buf = 0;
    for (int it = 0; it < nIter; ++it) {
        #pragma unroll
        for (int r = 0; r < 4; ++r) {
            uint4 ua; ua.x = f2tf(pa[r].x); ua.y = f2tf(pa[r].y);
                      ua.z = f2tf(pa[r].z); ua.w = f2tf(pa[r].w);
            *(uint4*)&smA[buf][adst[r]] = ua;
            uint4 ub; ub.x = f2tf(pb[r].x); ub.y = f2tf(pb[r].y);
                      ub.z = f2tf(pb[r].z); ub.w = f2tf(pb[r].w);
            *(uint4*)&smB[buf][bdst[r]] = ub;
        }
        __syncthreads();
        if (it + 1 < nIter) {
            #pragma unroll
            for (int r = 0; r < 4; ++r) {
                aptr[r] += adv_a; bptr[r] += adv_b;
                pa[r] = *(const float4*)aptr[r];
                pb[r] = *(const float4*)bptr[r];
            }
        }
        const unsigned* As = smA[buf];
        const unsigned* Bs = smB[buf];
        #pragma unroll
        for (int kk = 0; kk < 16; kk += 8) {
            unsigned af[4][4];
            const int k = kk + tg;
            #pragma unroll
            for (int mi = 0; mi < 4; ++mi) {
                int m = wm * 64 + mi * 16 + g;
                if (!AT) {
                    af[mi][0] = As[m * 20 + k];
                    af[mi][1] = As[(m + 8) * 20 + k];
                    af[mi][2] = As[m * 20 + k + 4];
                    af[mi][3] = As[(m + 8) * 20 + k + 4];
                } else {
                    af[mi][0] = As[k * 136 + m];
                    af[mi][1] = As[k * 136 + m + 8];
                    af[mi][2] = As[(k + 4) * 136 + m];
                    af[mi][3] = As[(k + 4) * 136 + m + 8];
                }
            }
            #pragma unroll
            for (int ni = 0; ni < 8; ++ni) {
                int n = wn * 64 + ni * 8 + g;
                unsigned b0, b1;
                if (!BT) { b0 = Bs[k * 136 + n]; b1 = Bs[(k + 4) * 136 + n]; }
                else     { b0 = Bs[n * 20 + k];  b1 = Bs[n * 20 + k + 4]; }
                #pragma unroll
                for (int mi = 0; mi < 4; ++mi)
                    mma8(acc[mi][ni], af[mi], b0, b1);
            }
        }
        buf ^= 1;
    }

    if (EPI == 2) {
        const int b = blockIdx.z;
        #pragma unroll
        for (int mi = 0; mi < 4; ++mi) {
            int row = r0 + wm * 64 + mi * 16 + g;
            #pragma unroll
            for (int rr = 0; rr < 2; ++rr) {
                int mel = row + rr * 8;
                float bb = bias[mel];
                float* op = C + ((long long)(b * 64 + (mel & 63)) * 20 + (mel >> 6)) * 2048;
                #pragma unroll
                for (int ni = 0; ni < 8; ++ni) {
                    int t = c0 + wn * 64 + ni * 8 + 2 * tg;
                    float2 v;
                    v.x = acc[mi][ni][rr * 2 + 0] + bb;
                    v.y = acc[mi][ni][rr * 2 + 1] + bb;
                    *(float2*)(op + t) = v;
                }
            }
        }
    } else {
        C += blockIdx.z * sC;
        #pragma unroll
        for (int mi = 0; mi < 4; ++mi) {
            int row = r0 + wm * 64 + mi * 16 + g;
            #pragma unroll
            for (int ni = 0; ni < 8; ++ni) {
                int col = c0 + wn * 64 + ni * 8 + 2 * tg;
                float b0v = bias ? bias[col] : 0.f;
                float b1v = bias ? bias[col + 1] : 0.f;
                float2 v0, v1;
                v0.x = alpha * acc[mi][ni][0] + b0v;
                v0.y = alpha * acc[mi][ni][1] + b1v;
                v1.x = alpha * acc[mi][ni][2] + b0v;
                v1.y = alpha * acc[mi][ni][3] + b1v;
                *(float2*)(C + (long long)row * ldc + col)       = v0;
                *(float2*)(C + (long long)(row + 8) * ldc + col) = v1;
            }
        }
    }
}

// -------- masked softmax over S=1024 per (b,t) row ---------------------------
__global__ __launch_bounds__(256) void softmax_rows(float* __restrict__ att)
{
    const int row = blockIdx.x;
    const int b = row >> 11;
    float* p = att + (long long)row * 1024;
    const int len = g_len[b];
    const int tid = threadIdx.x;
    const int s0 = tid * 4;
    float4 v = ((const float4*)p)[tid];
    float vals[4] = {v.x, v.y, v.z, v.w};
    float mx = -1e30f;
    #pragma unroll
    for (int u = 0; u < 4; ++u)
        if (s0 + u < len && vals[u] > mx) mx = vals[u];
    __shared__ float red[8];
    #pragma unroll
    for (int off = 16; off > 0; off >>= 1)
        mx = fmaxf(mx, __shfl_xor_sync(0xffffffffu, mx, off));
    if ((tid & 31) == 0) red[tid >> 5] = mx;
    __syncthreads();
    mx = red[0];
    #pragma unroll
    for (int i = 1; i < 8; ++i) mx = fmaxf(mx, red[i]);
    __syncthreads();
    float sum = 0.f;
    #pragma unroll
    for (int u = 0; u < 4; ++u) {
        float e = (s0 + u < len) ? __expf(vals[u] - mx) : 0.f;
        vals[u] = e; sum += e;
    }
    #pragma unroll
    for (int off = 16; off > 0; off >>= 1)
        sum += __shfl_xor_sync(0xffffffffu, sum, off);
    if ((tid & 31) == 0) red[tid >> 5] = sum;
    __syncthreads();
    sum = 0.f;
    #pragma unroll
    for (int i = 0; i < 8; ++i) sum += red[i];
    const float inv = 1.f / sum;
    v.x = vals[0] * inv; v.y = vals[1] * inv;
    v.z = vals[2] * inv; v.w = vals[3] * inv;
    ((float4*)p)[tid] = v;
}

// ---------------------------------------------------------------------------
extern "C" void kernel_launch(void* const* d_in, const int* in_sizes, int n_in,
                              void* d_out, int out_size)
{
    const float* ph      = (const float*)d_in[0];   // [16,1024,512]
    const float* g       = (const float*)d_in[1];   // [16,2560,2048] (c*f, t)
    const void*  lengths = d_in[2];
    const float* Wk      = (const float*)d_in[3];
    const float* bk      = (const float*)d_in[4];
    const float* Wv      = (const float*)d_in[5];
    const float* bv      = (const float*)d_in[6];
    const float* Wq      = (const float*)d_in[7];
    const float* bq      = (const float*)d_in[8];
    const float* Wmel    = (const float*)d_in[9];
    const float* bmel    = (const float*)d_in[10];
    float* out = (float*)d_out;

    float *k_, *v_, *q_, *att_, *val_;
    cudaGetSymbolAddress((void**)&k_,   g_k);
    cudaGetSymbolAddress((void**)&v_,   g_v);
    cudaGetSymbolAddress((void**)&q_,   g_q);
    cudaGetSymbolAddress((void**)&att_, g_att);
    cudaGetSymbolAddress((void**)&val_, g_val);

    const dim3 th(128);

    normalize_lengths<<<1, 1>>>(lengths);

    // k = ph@Wk + bk ; v = ph@Wv + bv   (A rm [16384,512], B [512,512])
    tc_gemm<0,0,0><<<dim3(4, 128, 1), th>>>(ph, Wk, bk, k_,
        512, 512, 512, 512, 0, 0, 0, 1.f);
    tc_gemm<0,0,0><<<dim3(4, 128, 1), th>>>(ph, Wv, bv, v_,
        512, 512, 512, 512, 0, 0, 0, 1.f);

    // q = g^T@Wq + bq  (A k-major [2560,2048] per batch, B [2560,512])
    tc_gemm<1,0,0><<<dim3(4, 16, 16), th>>>(g, Wq, bq, q_,
        2560, 2048, 512, 512, 2560LL * 2048, 0, 2048LL * 512, 1.f);

    // att = scale * q@k^T  (A rm [2048,512], B^T [1024,512] per batch)
    tc_gemm<0,1,0><<<dim3(8, 16, 16), th>>>(q_, k_, nullptr, att_,
        512, 512, 512, 1024, 2048LL * 512, 1024LL * 512, 2048LL * 1024,
        0.04419417382415922f);

    softmax_rows<<<32768, 256>>>(att_);

    // value = att@v  (A rm [2048,1024], B [1024,512] per batch)
    tc_gemm<0,0,0><<<dim3(4, 16, 16), th>>>(att_, v_, nullptr, val_,
        1024, 1024, 512, 512, 2048LL * 1024, 1024LL * 512, 2048LL * 512, 1.f);

    // out^T = Wmel^T @ val^T + bmel, with fused permute
    // (A k-major [512,1280] shared, B^T = val [2048,512] per batch, cols = t)
    tc_gemm<1,1,2><<<dim3(16, 10, 16), th>>>(Wmel, val_, bmel, out,
        512, 1280, 512, 2048, 0, 2048LL * 512, 0, 1.f);
}

// round 10
// speedup vs baseline: 1.2700x; 1.2700x over previous
#include <cuda_runtime.h>
#include <cstdint>

// ---------------- scratch (device globals; zero-initialized, no alloc) -------
__device__ float g_k  [16LL * 1024 * 512];
__device__ float g_v  [16LL * 1024 * 512];
__device__ float g_q  [16LL * 2048 * 512];
__device__ float g_att[16LL * 2048 * 1024];
__device__ float g_val[16LL * 2048 * 512];
__device__ int   g_len[16];

// -------- lengths dtype sniffing (reference says int64; JAX x64-off -> int32)
__global__ void normalize_lengths(const void* __restrict__ lp)
{
    const long long* l8 = (const long long*)lp;
    const int*       l4 = (const int*)lp;
    bool ok64 = true;
    for (int i = 0; i < 8; ++i) {
        long long v = l8[i];
        if (v < 1 || v > 1024) ok64 = false;
    }
    if (ok64) { for (int i = 0; i < 16; ++i) g_len[i] = (int)l8[i]; }
    else      { for (int i = 0; i < 16; ++i) g_len[i] = l4[i]; }
}

// ---------------------------------------------------------------------------
__device__ __forceinline__ unsigned f2tf(float x) {
    unsigned u; asm("cvt.rna.tf32.f32 %0, %1;" : "=r"(u) : "f"(x)); return u;
}
__device__ __forceinline__ void mma8(float* c, const unsigned* a,
                                     unsigned b0, unsigned b1) {
    asm volatile(
        "mma.sync.aligned.m16n8k8.row.col.f32.tf32.tf32.f32 "
        "{%0,%1,%2,%3},{%4,%5,%6,%7},{%8,%9},{%0,%1,%2,%3};"
        : "+f"(c[0]), "+f"(c[1]), "+f"(c[2]), "+f"(c[3])
        : "r"(a[0]), "r"(a[1]), "r"(a[2]), "r"(a[3]), "r"(b0), "r"(b1));
}

// ---------------------------------------------------------------------------
// tf32 tensor-core GEMM, 128x128x16 CTA tiles, 128 threads (4 warps 2m x 2n),
// warp tile 64x64, m16n8k8. Double-buffered smem, LDG prefetch, 2 CTAs/SM.
// AT=0: A row-major [M,K]; AT=1: A k-major [K,M]. BT=0: B [K,N]; BT=1: B^T [N,K].
// EPI=0: row-major C (+bias); EPI=2: mel permute (rows=mel, cols=t).
// LM: length-aware skipping. 0=none; 1=skip M-blocks with s0>=len (k/v proj,
// rows=b*1024+s); 2=skip CTA when c0>=len[z] (att cols=s, masked by softmax);
// 3=clamp K iters to ceil(len[z]/16) (value GEMM, att cols beyond len are 0).
template<int AT, int BT, int EPI, int LM>
__global__ __launch_bounds__(128, 2) void tc_gemm(
    const float* __restrict__ A, const float* __restrict__ Bm,
    const float* __restrict__ bias, float* __restrict__ C,
    int K, int lda, int ldb, int ldc,
    long long sA, long long sB, long long sC, float alpha)
{
    constexpr int ASZ = AT ? 16 * 136 : 128 * 20;
    constexpr int BSZ = BT ? 128 * 20 : 16 * 136;
    __shared__ unsigned smA[2][ASZ];
    __shared__ unsigned smB[2][BSZ];

    const int r0 = blockIdx.y * 128, c0 = blockIdx.x * 128;
    if (LM == 1) { if ((r0 & 1023) >= g_len[r0 >> 10]) return; }
    if (LM == 2) { if (c0 >= g_len[blockIdx.z]) return; }

    A  += blockIdx.z * sA;
    Bm += blockIdx.z * sB;
    const int tid  = threadIdx.x;
    const int lane = tid & 31, warp = tid >> 5;
    const int g  = lane >> 2, tg = lane & 3;
    const int wm = warp & 1,  wn = warp >> 1;

    const float* aptr[4]; unsigned adst[4];
    const float* bptr[4]; unsigned bdst[4];
    #pragma unroll
    for (int r = 0; r < 4; ++r) {
        int i = tid + 128 * r;
        if (!AT) { int m = i >> 2, kq = (i & 3) * 4;
                   aptr[r] = A + (long long)(r0 + m) * lda + kq;
                   adst[r] = m * 20 + kq; }
        else     { int k = i >> 5, m4 = (i & 31) * 4;
                   aptr[r] = A + (long long)k * lda + r0 + m4;
                   adst[r] = k * 136 + m4; }
        if (!BT) { int k = i >> 5, n4 = (i & 31) * 4;
                   bptr[r] = Bm + (long long)k * ldb + c0 + n4;
                   bdst[r] = k * 136 + n4; }
        else     { int n = i >> 2, kq = (i & 3) * 4;
                   bptr[r] = Bm + (long long)(c0 + n) * ldb + kq;
                   bdst[r] = n * 20 + kq; }
    }
    const long long adv_a = AT ? 16LL * lda : 16LL;
    const long long adv_b = BT ? 16LL : 16LL * ldb;

    float acc[4][8][4] = {};
    int nIter = K >> 4;
    if (LM == 3) {
        int nl = (g_len[blockIdx.z] + 15) >> 4;
        if (nl < nIter) nIter = nl;
    }

    float4 pa[4], pb[4];
    #pragma unroll
    for (int r = 0; r < 4; ++r) {
        pa[r] = *(const float4*)aptr[r];
        pb[r] = *(const float4*)bptr[r];
    }

    int buf = 0;
    for (int it = 0; it < nIter; ++it) {
        #pragma unroll
        for (int r = 0; r < 4; ++r) {
            uint4 ua; ua.x = f2tf(pa[r].x); ua.y = f2tf(pa[r].y);
                      ua.z = f2tf(pa[r].z); ua.w = f2tf(pa[r].w);
            *(uint4*)&smA[buf][adst[r]] = ua;
            uint4 ub; ub.x = f2tf(pb[r].x); ub.y = f2tf(pb[r].y);
                      ub.z = f2tf(pb[r].z); ub.w = f2tf(pb[r].w);
            *(uint4*)&smB[buf][bdst[r]] = ub;
        }
        __syncthreads();
        if (it + 1 < nIter) {
            #pragma unroll
            for (int r = 0; r < 4; ++r) {
                aptr[r] += adv_a; bptr[r] += adv_b;
                pa[r] = *(const float4*)aptr[r];
                pb[r] = *(const float4*)bptr[r];
            }
        }
        const unsigned* As = smA[buf];
        const unsigned* Bs = smB[buf];
        #pragma unroll
        for (int kk = 0; kk < 16; kk += 8) {
            unsigned af[4][4];
            const int k = kk + tg;
            #pragma unroll
            for (int mi = 0; mi < 4; ++mi) {
                int m = wm * 64 + mi * 16 + g;
                if (!AT) {
                    af[mi][0] = As[m * 20 + k];
                    af[mi][1] = As[(m + 8) * 20 + k];
                    af[mi][2] = As[m * 20 + k + 4];
                    af[mi][3] = As[(m + 8) * 20 + k + 4];
                } else {
                    af[mi][0] = As[k * 136 + m];
                    af[mi][1] = As[k * 136 + m + 8];
                    af[mi][2] = As[(k + 4) * 136 + m];
                    af[mi][3] = As[(k + 4) * 136 + m + 8];
                }
            }
            #pragma unroll
            for (int ni = 0; ni < 8; ++ni) {
                int n = wn * 64 + ni * 8 + g;
                unsigned b0, b1;
                if (!BT) { b0 = Bs[k * 136 + n]; b1 = Bs[(k + 4) * 136 + n]; }
                else     { b0 = Bs[n * 20 + k];  b1 = Bs[n * 20 + k + 4]; }
                #pragma unroll
                for (int mi = 0; mi < 4; ++mi)
                    mma8(acc[mi][ni], af[mi], b0, b1);
            }
        }
        buf ^= 1;
    }

    if (EPI == 2) {
        const int b = blockIdx.z;
        #pragma unroll
        for (int mi = 0; mi < 4; ++mi) {
            int row = r0 + wm * 64 + mi * 16 + g;
            #pragma unroll
            for (int rr = 0; rr < 2; ++rr) {
                int mel = row + rr * 8;
                float bb = bias[mel];
                float* op = C + ((long long)(b * 64 + (mel & 63)) * 20 + (mel >> 6)) * 2048;
                #pragma unroll
                for (int ni = 0; ni < 8; ++ni) {
                    int t = c0 + wn * 64 + ni * 8 + 2 * tg;
                    float2 v;
                    v.x = acc[mi][ni][rr * 2 + 0] + bb;
                    v.y = acc[mi][ni][rr * 2 + 1] + bb;
                    *(float2*)(op + t) = v;
                }
            }
        }
    } else {
        C += blockIdx.z * sC;
        #pragma unroll
        for (int mi = 0; mi < 4; ++mi) {
            int row = r0 + wm * 64 + mi * 16 + g;
            #pragma unroll
            for (int ni = 0; ni < 8; ++ni) {
                int col = c0 + wn * 64 + ni * 8 + 2 * tg;
                float b0v = bias ? bias[col] : 0.f;
                float b1v = bias ? bias[col + 1] : 0.f;
                float2 v0, v1;
                v0.x = alpha * acc[mi][ni][0] + b0v;
                v0.y = alpha * acc[mi][ni][1] + b1v;
                v1.x = alpha * acc[mi][ni][2] + b0v;
                v1.y = alpha * acc[mi][ni][3] + b1v;
                *(float2*)(C + (long long)row * ldc + col)       = v0;
                *(float2*)(C + (long long)(row + 8) * ldc + col) = v1;
            }
        }
    }
}

// -------- masked softmax over S=1024 per (b,t) row ---------------------------
__global__ __launch_bounds__(256) void softmax_rows(float* __restrict__ att)
{
    const int row = blockIdx.x;
    const int b = row >> 11;
    float* p = att + (long long)row * 1024;
    const int len = g_len[b];
    const int tid = threadIdx.x;
    const int s0 = tid * 4;
    float4 v = ((const float4*)p)[tid];
    float vals[4] = {v.x, v.y, v.z, v.w};
    float mx = -1e30f;
    #pragma unroll
    for (int u = 0; u < 4; ++u)
        if (s0 + u < len && vals[u] > mx) mx = vals[u];
    __shared__ float red[8];
    #pragma unroll
    for (int off = 16; off > 0; off >>= 1)
        mx = fmaxf(mx, __shfl_xor_sync(0xffffffffu, mx, off));
    if ((tid & 31) == 0) red[tid >> 5] = mx;
    __syncthreads();
    mx = red[0];
    #pragma unroll
    for (int i = 1; i < 8; ++i) mx = fmaxf(mx, red[i]);
    __syncthreads();
    float sum = 0.f;
    #pragma unroll
    for (int u = 0; u < 4; ++u) {
        float e = (s0 + u < len) ? __expf(vals[u] - mx) : 0.f;
        vals[u] = e; sum += e;
    }
    #pragma unroll
    for (int off = 16; off > 0; off >>= 1)
        sum += __shfl_xor_sync(0xffffffffu, sum, off);
    if ((tid & 31) == 0) red[tid >> 5] = sum;
    __syncthreads();
    sum = 0.f;
    #pragma unroll
    for (int i = 0; i < 8; ++i) sum += red[i];
    const float inv = 1.f / sum;
    v.x = vals[0] * inv; v.y = vals[1] * inv;
    v.z = vals[2] * inv; v.w = vals[3] * inv;
    ((float4*)p)[tid] = v;
}

// ---------------------------------------------------------------------------
extern "C" void kernel_launch(void* const* d_in, const int* in_sizes, int n_in,
                              void* d_out, int out_size)
{
    const float* ph      = (const float*)d_in[0];
    const float* g       = (const float*)d_in[1];
    const void*  lengths = d_in[2];
    const float* Wk      = (const float*)d_in[3];
    const float* bk      = (const float*)d_in[4];
    const float* Wv      = (const float*)d_in[5];
    const float* bv      = (const float*)d_in[6];
    const float* Wq      = (const float*)d_in[7];
    const float* bq      = (const float*)d_in[8];
    const float* Wmel    = (const float*)d_in[9];
    const float* bmel    = (const float*)d_in[10];
    float* out = (float*)d_out;

    float *k_, *v_, *q_, *att_, *val_;
    cudaGetSymbolAddress((void**)&k_,   g_k);
    cudaGetSymbolAddress((void**)&v_,   g_v);
    cudaGetSymbolAddress((void**)&q_,   g_q);
    cudaGetSymbolAddress((void**)&att_, g_att);
    cudaGetSymbolAddress((void**)&val_, g_val);

    const dim3 th(128);

    normalize_lengths<<<1, 1>>>(lengths);

    // k = ph@Wk + bk ; v = ph@Wv + bv  (skip M-blocks with s0 >= len[b])
    tc_gemm<0,0,0,1><<<dim3(4, 128, 1), th>>>(ph, Wk, bk, k_,
        512, 512, 512, 512, 0, 0, 0, 1.f);
    tc_gemm<0,0,0,1><<<dim3(4, 128, 1), th>>>(ph, Wv, bv, v_,
        512, 512, 512, 512, 0, 0, 0, 1.f);

    // q = g^T@Wq + bq  (A k-major per batch)
    tc_gemm<1,0,0,0><<<dim3(4, 16, 16), th>>>(g, Wq, bq, q_,
        2560, 2048, 512, 512, 2560LL * 2048, 0, 2048LL * 512, 1.f);

    // att = scale * q@k^T  (skip CTAs with c0 >= len[b]; softmax masks them)
    tc_gemm<0,1,0,2><<<dim3(8, 16, 16), th>>>(q_, k_, nullptr, att_,
        512, 512, 512, 1024, 2048LL * 512, 1024LL * 512, 2048LL * 1024,
        0.04419417382415922f);

    softmax_rows<<<32768, 256>>>(att_);

    // value = att@v  (K clamped to ceil(len/16); att cols beyond len are 0)
    tc_gemm<0,0,0,3><<<dim3(4, 16, 16), th>>>(att_, v_, nullptr, val_,
        1024, 1024, 512, 512, 2048LL * 1024, 1024LL * 512, 2048LL * 512, 1.f);

    // out = permute(value@Wmel + bmel)
    tc_gemm<1,1,2,0><<<dim3(16, 10, 16), th>>>(Wmel, val_, bmel, out,
        512, 1280, 512, 2048, 0, 2048LL * 512, 0, 1.f);
}

// round 11
// speedup vs baseline: 1.4071x; 1.1079x over previous
#include <cuda_runtime.h>
#include <cstdint>

// ---------------- scratch (device globals; zero-initialized, no alloc) -------
__device__ float g_k   [16LL * 1024 * 512];
__device__ float g_v   [16LL * 1024 * 512];
__device__ float g_q   [16LL * 2048 * 512];
__device__ float g_att [16LL * 2048 * 1024];
__device__ float g_vmel[16LL * 1024 * 1280];
__device__ int   g_len[16];

// -------- lengths dtype sniffing (reference says int64; JAX x64-off -> int32)
__global__ void normalize_lengths(const void* __restrict__ lp)
{
    const long long* l8 = (const long long*)lp;
    const int*       l4 = (const int*)lp;
    bool ok64 = true;
    for (int i = 0; i < 8; ++i) {
        long long v = l8[i];
        if (v < 1 || v > 1024) ok64 = false;
    }
    if (ok64) { for (int i = 0; i < 16; ++i) g_len[i] = (int)l8[i]; }
    else      { for (int i = 0; i < 16; ++i) g_len[i] = l4[i]; }
}

// ---------------------------------------------------------------------------
__device__ __forceinline__ unsigned f2tf(float x) {
    unsigned u; asm("cvt.rna.tf32.f32 %0, %1;" : "=r"(u) : "f"(x)); return u;
}
__device__ __forceinline__ void mma8(float* c, const unsigned* a,
                                     unsigned b0, unsigned b1) {
    asm volatile(
        "mma.sync.aligned.m16n8k8.row.col.f32.tf32.tf32.f32 "
        "{%0,%1,%2,%3},{%4,%5,%6,%7},{%8,%9},{%0,%1,%2,%3};"
        : "+f"(c[0]), "+f"(c[1]), "+f"(c[2]), "+f"(c[3])
        : "r"(a[0]), "r"(a[1]), "r"(a[2]), "r"(a[3]), "r"(b0), "r"(b1));
}

// ---------------------------------------------------------------------------
// tf32 tensor-core GEMM, 128x128x16 CTA tiles, 128 threads (4 warps 2m x 2n),
// warp tile 64x64, m16n8k8. Double-buffered smem, LDG prefetch, 2 CTAs/SM.
// AT=0: A row-major [M,K]; AT=1: A k-major [K,M]. BT=0: B [K,N]; BT=1: B^T [N,K].
// EPI=0: row-major C (+bias); EPI=2: mel permute (rows=mel, cols=t).
// LM: 0=none; 1=skip M-blocks with (r0&1023)>=len[r0>>10] (rows are b*1024+s);
// 2=skip CTA when c0>=len[z]; 3=clamp K iters to ceil(len[z]/16);
// 4=skip CTA when r0>=len[z] (per-batch M rows = s).
template<int AT, int BT, int EPI, int LM>
__global__ __launch_bounds__(128, 2) void tc_gemm(
    const float* __restrict__ A, const float* __restrict__ Bm,
    const float* __restrict__ bias, float* __restrict__ C,
    int K, int lda, int ldb, int ldc,
    long long sA, long long sB, long long sC, float alpha)
{
    constexpr int ASZ = AT ? 16 * 136 : 128 * 20;
    constexpr int BSZ = BT ? 128 * 20 : 16 * 136;
    __shared__ unsigned smA[2][ASZ];
    __shared__ unsigned smB[2][BSZ];

    const int r0 = blockIdx.y * 128, c0 = blockIdx.x * 128;
    if (LM == 1) { if ((r0 & 1023) >= g_len[r0 >> 10]) return; }
    if (LM == 2) { if (c0 >= g_len[blockIdx.z]) return; }
    if (LM == 4) { if (r0 >= g_len[blockIdx.z]) return; }

    A  += blockIdx.z * sA;
    Bm += blockIdx.z * sB;
    const int tid  = threadIdx.x;
    const int lane = tid & 31, warp = tid >> 5;
    const int g  = lane >> 2, tg = lane & 3;
    const int wm = warp & 1,  wn = warp >> 1;

    const float* aptr[4]; unsigned adst[4];
    const float* bptr[4]; unsigned bdst[4];
    #pragma unroll
    for (int r = 0; r < 4; ++r) {
        int i = tid + 128 * r;
        if (!AT) { int m = i >> 2, kq = (i & 3) * 4;
                   aptr[r] = A + (long long)(r0 + m) * lda + kq;
                   adst[r] = m * 20 + kq; }
        else     { int k = i >> 5, m4 = (i & 31) * 4;
                   aptr[r] = A + (long long)k * lda + r0 + m4;
                   adst[r] = k * 136 + m4; }
        if (!BT) { int k = i >> 5, n4 = (i & 31) * 4;
                   bptr[r] = Bm + (long long)k * ldb + c0 + n4;
                   bdst[r] = k * 136 + n4; }
        else     { int n = i >> 2, kq = (i & 3) * 4;
                   bptr[r] = Bm + (long long)(c0 + n) * ldb + kq;
                   bdst[r] = n * 20 + kq; }
    }
    const long long adv_a = AT ? 16LL * lda : 16LL;
    const long long adv_b = BT ? 16LL : 16LL * ldb;

    float acc[4][8][4] = {};
    int nIter = K >> 4;
    if (LM == 3) {
        int nl = (g_len[blockIdx.z] + 15) >> 4;
        if (nl < nIter) nIter = nl;
    }

    float4 pa[4], pb[4];
    #pragma unroll
    for (int r = 0; r < 4; ++r) {
        pa[r] = *(const float4*)aptr[r];
        pb[r] = *(const float4*)bptr[r];
    }

    int buf = 0;
    for (int it = 0; it < nIter; ++it) {
        #pragma unroll
        for (int r = 0; r < 4; ++r) {
            uint4 ua; ua.x = f2tf(pa[r].x); ua.y = f2tf(pa[r].y);
                      ua.z = f2tf(pa[r].z); ua.w = f2tf(pa[r].w);
            *(uint4*)&smA[buf][adst[r]] = ua;
            uint4 ub; ub.x = f2tf(pb[r].x); ub.y = f2tf(pb[r].y);
                      ub.z = f2tf(pb[r].z); ub.w = f2tf(pb[r].w);
            *(uint4*)&smB[buf][bdst[r]] = ub;
        }
        // prefetch next tiles BEFORE the barrier (pa/pb already consumed)
        if (it + 1 < nIter) {
            #pragma unroll
            for (int r = 0; r < 4; ++r) {
                aptr[r] += adv_a; bptr[r] += adv_b;
                pa[r] = *(const float4*)aptr[r];
                pb[r] = *(const float4*)bptr[r];
            }
        }
        __syncthreads();
        const unsigned* As = smA[buf];
        const unsigned* Bs = smB[buf];
        #pragma unroll
        for (int kk = 0; kk < 16; kk += 8) {
            unsigned af[4][4];
            const int k = kk + tg;
            #pragma unroll
            for (int mi = 0; mi < 4; ++mi) {
                int m = wm * 64 + mi * 16 + g;
                if (!AT) {
                    af[mi][0] = As[m * 20 + k];
                    af[mi][1] = As[(m + 8) * 20 + k];
                    af[mi][2] = As[m * 20 + k + 4];
                    af[mi][3] = As[(m + 8) * 20 + k + 4];
                } else {
                    af[mi][0] = As[k * 136 + m];
                    af[mi][1] = As[k * 136 + m + 8];
                    af[mi][2] = As[(k + 4) * 136 + m];
                    af[mi][3] = As[(k + 4) * 136 + m + 8];
                }
            }
            #pragma unroll
            for (int ni = 0; ni < 8; ++ni) {
                int n = wn * 64 + ni * 8 + g;
                unsigned b0, b1;
                if (!BT) { b0 = Bs[k * 136 + n]; b1 = Bs[(k + 4) * 136 + n]; }
                else     { b0 = Bs[n * 20 + k];  b1 = Bs[n * 20 + k + 4]; }
                #pragma unroll
                for (int mi = 0; mi < 4; ++mi)
                    mma8(acc[mi][ni], af[mi], b0, b1);
            }
        }
        buf ^= 1;
    }

    if (EPI == 2) {
        const int b = blockIdx.z;
        #pragma unroll
        for (int mi = 0; mi < 4; ++mi) {
            int row = r0 + wm * 64 + mi * 16 + g;
            #pragma unroll
            for (int rr = 0; rr < 2; ++rr) {
                int mel = row + rr * 8;
                float bb = bias[mel];
                float* op = C + ((long long)(b * 64 + (mel & 63)) * 20 + (mel >> 6)) * 2048;
                #pragma unroll
                for (int ni = 0; ni < 8; ++ni) {
                    int t = c0 + wn * 64 + ni * 8 + 2 * tg;
                    float2 v;
                    v.x = acc[mi][ni][rr * 2 + 0] + bb;
                    v.y = acc[mi][ni][rr * 2 + 1] + bb;
                    *(float2*)(op + t) = v;
                }
            }
        }
    } else {
        C += blockIdx.z * sC;
        #pragma unroll
        for (int mi = 0; mi < 4; ++mi) {
            int row = r0 + wm * 64 + mi * 16 + g;
            #pragma unroll
            for (int ni = 0; ni < 8; ++ni) {
                int col = c0 + wn * 64 + ni * 8 + 2 * tg;
                float b0v = bias ? bias[col] : 0.f;
                float b1v = bias ? bias[col + 1] : 0.f;
                float2 v0, v1;
                v0.x = alpha * acc[mi][ni][0] + b0v;
                v0.y = alpha * acc[mi][ni][1] + b1v;
                v1.x = alpha * acc[mi][ni][2] + b0v;
                v1.y = alpha * acc[mi][ni][3] + b1v;
                *(float2*)(C + (long long)row * ldc + col)       = v0;
                *(float2*)(C + (long long)(row + 8) * ldc + col) = v1;
            }
        }
    }
}

// -------- masked softmax over S=1024 per (b,t) row, length-clamped -----------
// Only cols [0, roundup16(len)) are touched; downstream GEMM clamps K to the
// same bound, so cols beyond it are never read. Cols in [len, roundup16) get
// explicit zeros.
__global__ __launch_bounds__(256) void softmax_rows(float* __restrict__ att)
{
    const int row = blockIdx.x;
    const int b = row >> 11;
    float* p = att + (long long)row * 1024;
    const int len = g_len[b];
    const int lim = (len + 15) & ~15;
    const int tid = threadIdx.x;
    const int s0 = tid * 4;
    const bool act = s0 < lim;
    float4 v = make_float4(0.f, 0.f, 0.f, 0.f);
    if (act) v = ((const float4*)p)[tid];
    float vals[4] = {v.x, v.y, v.z, v.w};
    float mx = -1e30f;
    #pragma unroll
    for (int u = 0; u < 4; ++u)
        if (s0 + u < len && vals[u] > mx) mx = vals[u];
    __shared__ float red[8];
    #pragma unroll
    for (int off = 16; off > 0; off >>= 1)
        mx = fmaxf(mx, __shfl_xor_sync(0xffffffffu, mx, off));
    if ((tid & 31) == 0) red[tid >> 5] = mx;
    __syncthreads();
    mx = red[0];
    #pragma unroll
    for (int i = 1; i < 8; ++i) mx = fmaxf(mx, red[i]);
    __syncthreads();
    float sum = 0.f;
    #pragma unroll
    for (int u = 0; u < 4; ++u) {
        float e = (s0 + u < len) ? __expf(vals[u] - mx) : 0.f;
        vals[u] = e; sum += e;
    }
    #pragma unroll
    for (int off = 16; off > 0; off >>= 1)
        sum += __shfl_xor_sync(0xffffffffu, sum, off);
    if ((tid & 31) == 0) red[tid >> 5] = sum;
    __syncthreads();
    sum = 0.f;
    #pragma unroll
    for (int i = 0; i < 8; ++i) sum += red[i];
    const float inv = 1.f / sum;
    if (act) {
        v.x = vals[0] * inv; v.y = vals[1] * inv;
        v.z = vals[2] * inv; v.w = vals[3] * inv;
        ((float4*)p)[tid] = v;
    }
}

// ---------------------------------------------------------------------------
extern "C" void kernel_launch(void* const* d_in, const int* in_sizes, int n_in,
                              void* d_out, int out_size)
{
    const float* ph      = (const float*)d_in[0];
    const float* g       = (const float*)d_in[1];
    const void*  lengths = d_in[2];
    const float* Wk      = (const float*)d_in[3];
    const float* bk      = (const float*)d_in[4];
    const float* Wv      = (const float*)d_in[5];
    const float* bv      = (const float*)d_in[6];
    const float* Wq      = (const float*)d_in[7];
    const float* bq      = (const float*)d_in[8];
    const float* Wmel    = (const float*)d_in[9];
    const float* bmel    = (const float*)d_in[10];
    float* out = (float*)d_out;

    float *k_, *v_, *q_, *att_, *vmel_;
    cudaGetSymbolAddress((void**)&k_,    g_k);
    cudaGetSymbolAddress((void**)&v_,    g_v);
    cudaGetSymbolAddress((void**)&q_,    g_q);
    cudaGetSymbolAddress((void**)&att_,  g_att);
    cudaGetSymbolAddress((void**)&vmel_, g_vmel);

    const dim3 th(128);

    normalize_lengths<<<1, 1>>>(lengths);

    // k = ph@Wk + bk ; v = ph@Wv + bv  (skip s-blocks >= len[b])
    tc_gemm<0,0,0,1><<<dim3(4, 128, 1), th>>>(ph, Wk, bk, k_,
        512, 512, 512, 512, 0, 0, 0, 1.f);
    tc_gemm<0,0,0,1><<<dim3(4, 128, 1), th>>>(ph, Wv, bv, v_,
        512, 512, 512, 512, 0, 0, 0, 1.f);

    // q = g^T@Wq + bq  (A k-major per batch)
    tc_gemm<1,0,0,0><<<dim3(4, 16, 16), th>>>(g, Wq, bq, q_,
        2560, 2048, 512, 512, 2560LL * 2048, 0, 2048LL * 512, 1.f);

    // att = scale * q@k^T  (skip CTAs with c0 >= len[b])
    tc_gemm<0,1,0,2><<<dim3(8, 16, 16), th>>>(q_, k_, nullptr, att_,
        512, 512, 512, 1024, 2048LL * 512, 1024LL * 512, 2048LL * 1024,
        0.04419417382415922f);

    softmax_rows<<<32768, 256>>>(att_);

    // vmel = v@Wmel  (per batch [1024,1280]; skip s-blocks >= len[b]; no bias)
    tc_gemm<0,0,0,4><<<dim3(10, 8, 16), th>>>(v_, Wmel, nullptr, vmel_,
        512, 512, 1280, 1280, 1024LL * 512, 0, 1024LL * 1280, 1.f);

    // out = permute(att@vmel + bmel): rows=mel (A=vmel k-major), cols=t
    // (B=att row-major, BT=1), K=S clamped to ceil(len/16)*16
    tc_gemm<1,1,2,3><<<dim3(16, 10, 16), th>>>(vmel_, att_, bmel, out,
        1024, 1280, 1024, 2048, 1024LL * 1280, 2048LL * 1024, 0, 1.f);
}